// round 9
// baseline (speedup 1.0000x reference)
#include <cuda_runtime.h>
#include <math.h>

#define THREADS          128
#define WARPS            4
#define ROWS_PER_WARP    16
#define ROWS_PER_CHUNK   4
#define NCHUNKS          4                    // 4 chunks x 4 rows = 16 rows
#define CHUNK_BYTES      4096                 // 4 rows x 1KB, contiguous in gmem
#define CHUNK_Q          256                  // float4 per chunk
#define NBUF             2
#define MAX_BLOCKS       8192

__device__ double g_part[MAX_BLOCKS];
__device__ unsigned int g_count;              // zero at load; last block resets -> replay-safe

__device__ __forceinline__ float softplusf(float x) {
    return fmaxf(x, 0.0f) + log1pf(expf(-fabsf(x)));
}

// packed f32x2 helpers
__device__ __forceinline__ unsigned long long pack2(float lo, float hi) {
    unsigned long long r;
    asm("mov.b64 %0, {%1, %2};" : "=l"(r) : "f"(lo), "f"(hi));
    return r;
}
__device__ __forceinline__ void unpack2(unsigned long long v, float& lo, float& hi) {
    asm("mov.b64 {%0, %1}, %2;" : "=f"(lo), "=f"(hi) : "l"(v));
}
__device__ __forceinline__ unsigned long long fma2(unsigned long long a,
                                                   unsigned long long b,
                                                   unsigned long long c) {
    unsigned long long d;
    asm("fma.rn.f32x2 %0, %1, %2, %3;" : "=l"(d) : "l"(a), "l"(b), "l"(c));
    return d;
}
__device__ __forceinline__ unsigned long long add2(unsigned long long a,
                                                   unsigned long long b) {
    unsigned long long d;
    asm("add.rn.f32x2 %0, %1, %2;" : "=l"(d) : "l"(a), "l"(b));
    return d;
}

// ---- bulk-async (1D TMA-style) + mbarrier ----
__device__ __forceinline__ void mbar_init(unsigned int mbar, unsigned int count) {
    asm volatile("mbarrier.init.shared.b64 [%0], %1;" :: "r"(mbar), "r"(count) : "memory");
}
__device__ __forceinline__ void mbar_expect_tx(unsigned int mbar, unsigned int bytes) {
    asm volatile("mbarrier.arrive.expect_tx.shared.b64 _, [%0], %1;"
                 :: "r"(mbar), "r"(bytes) : "memory");
}
__device__ __forceinline__ void bulk_g2s(unsigned int dst_smem, const void* src,
                                         unsigned int bytes, unsigned int mbar) {
    asm volatile("cp.async.bulk.shared::cta.global.mbarrier::complete_tx::bytes "
                 "[%0], [%1], %2, [%3];"
                 :: "r"(dst_smem), "l"(src), "r"(bytes), "r"(mbar) : "memory");
}
__device__ __forceinline__ void mbar_wait(unsigned int mbar, unsigned int parity) {
    unsigned int done;
    asm volatile(
        "{\n\t.reg .pred p;\n\t"
        "mbarrier.try_wait.parity.acquire.cta.shared::cta.b64 p, [%1], %2;\n\t"
        "selp.b32 %0, 1, 0, p;\n\t}"
        : "=r"(done) : "r"(mbar), "r"(parity) : "memory");
    if (!done) {
        asm volatile(
            "{\n\t.reg .pred P1;\n\t"
            "W_%=:\n\t"
            "mbarrier.try_wait.parity.acquire.cta.shared::cta.b64 P1, [%0], %1, 0x989680;\n\t"
            "@P1 bra.uni D_%=;\n\t"
            "bra.uni W_%=;\n\t"
            "D_%=:\n\t}"
            :: "r"(mbar), "r"(parity) : "memory");
    }
}

__global__ void __launch_bounds__(THREADS, 7) sat_fused_kernel(
    const int* __restrict__ b1, const int* __restrict__ b2,
    const float* __restrict__ z1, const float* __restrict__ z2,
    const float* __restrict__ g1, const float* __restrict__ g2,
    float* __restrict__ out, int N)
{
    extern __shared__ float4 zbuf[];                   // [WARPS][NBUF][CHUNK_Q] = 32KB
    __shared__ unsigned long long mbar_store[WARPS * NBUF];

    const int tid  = threadIdx.x;
    const int lane = tid & 31;
    const int wib  = tid >> 5;

    const unsigned int mbar0 =
        (unsigned int)__cvta_generic_to_shared(&mbar_store[wib * NBUF]);
    const unsigned int sbuf0 =
        (unsigned int)__cvta_generic_to_shared(zbuf + wib * NBUF * CHUNK_Q);

    if (tid < WARPS * NBUF)
        mbar_init((unsigned int)__cvta_generic_to_shared(&mbar_store[tid]), 1u);
    __syncthreads();

    const int warpsPerStream = N / ROWS_PER_WARP;      // 4096
    const int gwarp  = blockIdx.x * WARPS + wib;
    const int stream = (gwarp >= warpsPerStream) ? 1 : 0;
    const int wloc   = gwarp - stream * warpsPerStream;
    const int base   = wloc * ROWS_PER_WARP;           // first row of this warp

    const int*   b  = stream ? b2 : b1;
    const float* z  = stream ? z2 : z1;
    const float* gS = stream ? g2 : g1;                // self pairing
    const float* gC = stream ? g1 : g2;                // cross pairing

    // preload my 16 batch ids
    int myb = (lane < ROWS_PER_WARP) ? b[base + lane] : 0;

    const char* zbase = (const char*)z + (size_t)base * 1024;   // 16KB contiguous
    const float4* gS4 = reinterpret_cast<const float4*>(gS);
    const float4* gC4 = reinterpret_cast<const float4*>(gC);

    const int rowc = lane >> 3;                        // row within chunk (0..3)
    const int col  = lane & 7;                         // column octet (0..7)

    // issue chunk c: one 4KB bulk copy
    auto issue = [&](int c) {
        const int buf = c & 1;
        mbar_expect_tx(mbar0 + buf * 8u, CHUNK_BYTES);
        bulk_g2s(sbuf0 + (unsigned int)buf * CHUNK_BYTES,
                 (const void*)(zbase + (size_t)c * CHUNK_BYTES),
                 CHUNK_BYTES, mbar0 + buf * 8u);
    };

    if (lane == 0) { issue(0); issue(1); }

    double accd = 0.0;

    #pragma unroll
    for (int c = 0; c < NCHUNKS; ++c) {
        mbar_wait(mbar0 + (c & 1) * 8u, (unsigned int)((c >> 1) & 1));

        const float4* buf = zbuf + (wib * NBUF + (c & 1)) * CHUNK_Q + rowc * 64;
        const int gidx = __shfl_sync(0xFFFFFFFFu, myb, c * ROWS_PER_CHUNK + rowc);
        const float4* gs = gS4 + (size_t)gidx * 64;
        const float4* gc = gC4 + (size_t)gidx * 64;

        unsigned long long vS = 0, vC = 0;
        #pragma unroll
        for (int k = 0; k < 8; ++k) {
            const int q = col * 8 + ((k + col) & 7);   // rotation: conflict-min LDS
            float4 zv = buf[q];
            float4 sv = __ldg(gs + q);
            float4 cv = __ldg(gc + q);
            unsigned long long zlo = pack2(zv.x, zv.y), zhi = pack2(zv.z, zv.w);
            vS = fma2(zlo, pack2(sv.x, sv.y), vS);
            vS = fma2(zhi, pack2(sv.z, sv.w), vS);
            vC = fma2(zlo, pack2(cv.x, cv.y), vC);
            vC = fma2(zhi, pack2(cv.z, cv.w), vC);
        }
        float sx, sy, cx, cy;
        unpack2(vS, sx, sy); unpack2(vC, cx, cy);
        unsigned long long w = pack2(sx + sy, cx + cy);   // (dS, dC) partial

        // reduce across the 8 lanes of this row (4 rows in parallel)
        #pragma unroll
        for (int off = 4; off > 0; off >>= 1)
            w = add2(w, __shfl_xor_sync(0xFFFFFFFFu, w, off));

        float dS, dC;
        unpack2(w, dS, dC);
        float t = softplusf(-dC) - softplusf(-dS);     // LOG2 cancels
        if (col != 0) t = 0.0f;                        // count each row once
        accd += (double)t * (double)t;

        __syncwarp();                                  // all reads done before re-stage
        if (c + 2 < NCHUNKS && lane == 0) issue(c + 2);
    }

    // block reduction
    #pragma unroll
    for (int off = 16; off > 0; off >>= 1)
        accd += __shfl_xor_sync(0xFFFFFFFFu, accd, off);

    __shared__ double sh[WARPS];
    __shared__ int s_isLast;
    if (lane == 0) sh[wib] = accd;
    __syncthreads();

    if (tid == 0) {
        double s = sh[0] + sh[1] + sh[2] + sh[3];
        g_part[blockIdx.x] = s;
        __threadfence();
        unsigned int old = atomicAdd(&g_count, 1u);
        s_isLast = (old == gridDim.x - 1) ? 1 : 0;
    }
    __syncthreads();

    if (s_isLast) {
        const int grid = gridDim.x;
        const int halfg = grid >> 1;                   // first half = stream 0
        double s0 = 0.0, s1 = 0.0;
        volatile double* vp = g_part;
        for (int i = tid; i < grid; i += THREADS) {
            double v = vp[i];
            if (i < halfg) s0 += v; else s1 += v;
        }
        #pragma unroll
        for (int off = 16; off > 0; off >>= 1) {
            s0 += __shfl_xor_sync(0xFFFFFFFFu, s0, off);
            s1 += __shfl_xor_sync(0xFFFFFFFFu, s1, off);
        }
        __shared__ double r0[WARPS], r1[WARPS];
        if (lane == 0) { r0[wib] = s0; r1[wib] = s1; }
        __syncthreads();
        if (tid == 0) {
            double S0 = r0[0] + r0[1] + r0[2] + r0[3];
            double S1 = r1[0] + r1[1] + r1[2] + r1[3];
            out[0] = (float)(sqrt(S0) + sqrt(S1));
            atomicExch(&g_count, 0u);                  // reset for next graph replay
        }
    }
}

extern "C" void kernel_launch(void* const* d_in, const int* in_sizes, int n_in,
                              void* d_out, int out_size) {
    const int*   b1 = (const int*)d_in[0];
    const int*   b2 = (const int*)d_in[1];
    const float* z1 = (const float*)d_in[2];
    const float* z2 = (const float*)d_in[3];
    const float* g1 = (const float*)d_in[4];
    const float* g2 = (const float*)d_in[5];
    float* out = (float*)d_out;

    const int N = in_sizes[0];                         // 65536
    const int rowsPerBlock = ROWS_PER_WARP * WARPS;    // 64
    const int grid = (2 * N) / rowsPerBlock;           // 2048
    const int smemBytes = WARPS * NBUF * CHUNK_BYTES;  // 32,768 B

    sat_fused_kernel<<<grid, THREADS, smemBytes>>>(b1, b2, z1, z2, g1, g2, out, N);
}

// round 10
// speedup vs baseline: 1.2520x; 1.2520x over previous
#include <cuda_runtime.h>
#include <math.h>

#define THREADS         128
#define WARPS           4
#define ROWS_PER_WARP   16
#define MAX_BLOCKS      8192

__device__ double g_part[MAX_BLOCKS];
__device__ unsigned int g_count;           // zero at load; last block resets -> replay-safe

__device__ __forceinline__ float softplusf(float x) {
    return fmaxf(x, 0.0f) + log1pf(expf(-fabsf(x)));
}

// packed f32x2 helpers
__device__ __forceinline__ unsigned long long pack2(float lo, float hi) {
    unsigned long long r;
    asm("mov.b64 %0, {%1, %2};" : "=l"(r) : "f"(lo), "f"(hi));
    return r;
}
__device__ __forceinline__ void unpack2(unsigned long long v, float& lo, float& hi) {
    asm("mov.b64 {%0, %1}, %2;" : "=f"(lo), "=f"(hi) : "l"(v));
}
__device__ __forceinline__ unsigned long long fma2(unsigned long long a,
                                                   unsigned long long b,
                                                   unsigned long long c) {
    unsigned long long d;
    asm("fma.rn.f32x2 %0, %1, %2, %3;" : "=l"(d) : "l"(a), "l"(b), "l"(c));
    return d;
}
__device__ __forceinline__ unsigned long long mul2(unsigned long long a,
                                                   unsigned long long b) {
    unsigned long long d;
    asm("mul.rn.f32x2 %0, %1, %2;" : "=l"(d) : "l"(a), "l"(b));
    return d;
}
__device__ __forceinline__ unsigned long long add2(unsigned long long a,
                                                   unsigned long long b) {
    unsigned long long d;
    asm("add.rn.f32x2 %0, %1, %2;" : "=l"(d) : "l"(a), "l"(b));
    return d;
}
__device__ __forceinline__ void prefetchL2(const void* p) {
    asm volatile("prefetch.global.L2 [%0];" :: "l"(p));
}

struct GRegs {
    unsigned long long s0, s1, s2, s3;   // gSelf row (8 f32 pairs)
    unsigned long long c0, c1, c2, c3;   // gCross row
};

__device__ __forceinline__ void loadG(GRegs& g, const float4* gS4, const float4* gC4,
                                      int gidx, int lane) {
    const float4* gs = gS4 + (size_t)gidx * 64;
    const float4* gc = gC4 + (size_t)gidx * 64;
    float4 a = __ldg(gs + lane), bq = __ldg(gs + 32 + lane);
    g.s0 = pack2(a.x, a.y); g.s1 = pack2(a.z, a.w);
    g.s2 = pack2(bq.x, bq.y); g.s3 = pack2(bq.z, bq.w);
    a = __ldg(gc + lane); bq = __ldg(gc + 32 + lane);
    g.c0 = pack2(a.x, a.y); g.c1 = pack2(a.z, a.w);
    g.c2 = pack2(bq.x, bq.y); g.c3 = pack2(bq.z, bq.w);
}

// compute row: dots vs cached g, 5-stage packed butterfly; lane==r keeps result
__device__ __forceinline__ void rowCalc(int r, float4 za, float4 zb, const GRegs& g,
                                        int lane, unsigned long long& myW) {
    unsigned long long z0 = pack2(za.x, za.y), z1p = pack2(za.z, za.w);
    unsigned long long z2 = pack2(zb.x, zb.y), z3 = pack2(zb.z, zb.w);
    unsigned long long vS = mul2(z0, g.s0);
    vS = fma2(z1p, g.s1, vS); vS = fma2(z2, g.s2, vS); vS = fma2(z3, g.s3, vS);
    unsigned long long vC = mul2(z0, g.c0);
    vC = fma2(z1p, g.c1, vC); vC = fma2(z2, g.c2, vC); vC = fma2(z3, g.c3, vC);
    float sx, sy, cx, cy;
    unpack2(vS, sx, sy); unpack2(vC, cx, cy);
    unsigned long long w = pack2(sx + sy, cx + cy);
    #pragma unroll
    for (int off = 16; off > 0; off >>= 1)
        w = add2(w, __shfl_xor_sync(0xFFFFFFFFu, w, off));
    if (lane == r) myW = w;
}

__global__ void __launch_bounds__(THREADS, 7) sat_fused_kernel(
    const int* __restrict__ b1, const int* __restrict__ b2,
    const float* __restrict__ z1, const float* __restrict__ z2,
    const float* __restrict__ g1, const float* __restrict__ g2,
    float* __restrict__ out, int N)
{
    const int tid  = threadIdx.x;
    const int lane = tid & 31;
    const int wib  = tid >> 5;

    const int warpsPerStream = N / ROWS_PER_WARP;      // 4096
    const int gwarp  = blockIdx.x * WARPS + wib;
    const int stream = (gwarp >= warpsPerStream) ? 1 : 0;
    const int wloc   = gwarp - stream * warpsPerStream;
    const int base   = wloc * ROWS_PER_WARP;

    const int*   b  = stream ? b2 : b1;
    const float* z  = stream ? z2 : z1;
    const float* gS = stream ? g2 : g1;
    const float* gC = stream ? g1 : g2;

    const int myb = b[base + (lane & 15)];             // lanes 16-31 mirror 0-15
    const int g0  = __shfl_sync(0xFFFFFFFFu, myb, 0);
    const bool allSame = __all_sync(0xFFFFFFFFu, myb == g0);

    const float4* z4  = reinterpret_cast<const float4*>(z) + (size_t)base * 64;
    const float4* gS4 = reinterpret_cast<const float4*>(gS);
    const float4* gC4 = reinterpret_cast<const float4*>(gC);
    const char*   zby = (const char*)z4;

    unsigned long long myW = 0;
    GRegs g;

    if (allSame) {
        // FAST PATH (~88% of warps): one g load, branch-free pipelined 16 rows
        loadG(g, gS4, gC4, g0, lane);
        #pragma unroll
        for (int bt = 0; bt < 8; ++bt) {
            if (bt < 6 && lane < 16)                   // prefetch 2 batches ahead
                prefetchL2(zby + (size_t)(bt + 2) * 2048 + (size_t)lane * 128);
            const float4* r0 = z4 + (size_t)(2 * bt) * 64;
            float4 a0 = __ldcs(r0 + lane);
            float4 b0 = __ldcs(r0 + 32 + lane);
            float4 a1 = __ldcs(r0 + 64 + lane);
            float4 b1 = __ldcs(r0 + 96 + lane);
            rowCalc(2 * bt,     a0, b0, g, lane, myW);
            rowCalc(2 * bt + 1, a1, b1, g, lane, myW);
        }
    } else {
        // SLOW PATH: per-row group check (warp-uniform branch)
        int cur = -1;
        #pragma unroll
        for (int r = 0; r < ROWS_PER_WARP; ++r) {
            if ((r & 1) == 0 && r < 12 && lane < 16)
                prefetchL2(zby + (size_t)(r + 4) * 1024 + (size_t)lane * 128);
            const int gidx = __shfl_sync(0xFFFFFFFFu, myb, r);
            if (gidx != cur) { cur = gidx; loadG(g, gS4, gC4, gidx, lane); }
            const float4* rr = z4 + (size_t)r * 64;
            float4 za = __ldcs(rr + lane);
            float4 zb = __ldcs(rr + 32 + lane);
            rowCalc(r, za, zb, g, lane, myW);
        }
    }

    // lanes 0..15 hold their row's (dS,dC); others hold (0,0) -> t == 0 exactly
    float dS, dC;
    unpack2(myW, dS, dC);
    const float t = softplusf(-dC) - softplusf(-dS);   // LOG2 cancels in the diff
    double accd = (double)t * (double)t;

    #pragma unroll
    for (int off = 16; off > 0; off >>= 1)
        accd += __shfl_xor_sync(0xFFFFFFFFu, accd, off);

    __shared__ double sh[WARPS];
    __shared__ int s_isLast;
    if (lane == 0) sh[wib] = accd;
    __syncthreads();

    if (tid == 0) {
        double s = sh[0] + sh[1] + sh[2] + sh[3];
        g_part[blockIdx.x] = s;
        __threadfence();
        unsigned int old = atomicAdd(&g_count, 1u);
        s_isLast = (old == gridDim.x - 1) ? 1 : 0;
    }
    __syncthreads();

    if (s_isLast) {
        const int grid = gridDim.x;
        const int halfg = grid >> 1;                   // first half = stream 0
        double s0 = 0.0, s1 = 0.0;
        volatile double* vp = g_part;
        for (int i = tid; i < grid; i += THREADS) {
            double v = vp[i];
            if (i < halfg) s0 += v; else s1 += v;
        }
        #pragma unroll
        for (int off = 16; off > 0; off >>= 1) {
            s0 += __shfl_xor_sync(0xFFFFFFFFu, s0, off);
            s1 += __shfl_xor_sync(0xFFFFFFFFu, s1, off);
        }
        __shared__ double r0s[WARPS], r1s[WARPS];
        if (lane == 0) { r0s[wib] = s0; r1s[wib] = s1; }
        __syncthreads();
        if (tid == 0) {
            double S0 = r0s[0] + r0s[1] + r0s[2] + r0s[3];
            double S1 = r1s[0] + r1s[1] + r1s[2] + r1s[3];
            out[0] = (float)(sqrt(S0) + sqrt(S1));
            atomicExch(&g_count, 0u);                  // reset for next graph replay
        }
    }
}

extern "C" void kernel_launch(void* const* d_in, const int* in_sizes, int n_in,
                              void* d_out, int out_size) {
    const int*   b1 = (const int*)d_in[0];
    const int*   b2 = (const int*)d_in[1];
    const float* z1 = (const float*)d_in[2];
    const float* z2 = (const float*)d_in[3];
    const float* g1 = (const float*)d_in[4];
    const float* g2 = (const float*)d_in[5];
    float* out = (float*)d_out;

    const int N = in_sizes[0];                         // 65536
    const int rowsPerBlock = ROWS_PER_WARP * WARPS;    // 64
    const int grid = (2 * N) / rowsPerBlock;           // 2048

    sat_fused_kernel<<<grid, THREADS>>>(b1, b2, z1, z2, g1, g2, out, N);
}